// round 4
// baseline (speedup 1.0000x reference)
#include <cuda_runtime.h>

#define NN 8192
#define FF 128
#define PP 16

// Scratch: u[i] = concat(alpha_row[i]*nf[i], (gamma_row[i]/F)*diff[i])
//          v[i] = concat(nf[i],              diff[i])
// act-edge value = dot(u[src], v[dst])  (length 2F = 256)
__device__ float g_u[NN * 2 * FF];
__device__ float g_v[NN * 2 * FF];
__device__ float g_nbeta[NN];   // -beta_row, pre-negated

__global__ void prep_kernel(const float* __restrict__ feature,
                            const float* __restrict__ next_feature,
                            const float* __restrict__ persona_t,
                            const float* __restrict__ alpha,
                            const float* __restrict__ beta,
                            const float* __restrict__ gamma) {
    int row = blockIdx.x;
    int t = threadIdx.x;                     // 0..127, one element per thread
    float nfv = next_feature[row * FF + t];
    float fv  = feature[row * FF + t];
    float d = fv - nfv;

    // block-reduce sum of squares of next_feature row
    float s = nfv * nfv;
    #pragma unroll
    for (int o = 16; o; o >>= 1) s += __shfl_xor_sync(0xffffffffu, s, o);
    __shared__ float warp_s[4];
    int w = t >> 5, l = t & 31;
    if (l == 0) warp_s[w] = s;
    __syncthreads();
    float sumsq = warp_s[0] + warp_s[1] + warp_s[2] + warp_s[3];
    float inv = rsqrtf(sumsq);
    float nf1 = nfv * inv;
    // reference normalizes twice (idempotent up to fp rounding); replicate:
    float s2 = nf1 * nf1;
    #pragma unroll
    for (int o = 16; o; o >>= 1) s2 += __shfl_xor_sync(0xffffffffu, s2, o);
    __shared__ float warp_s2[4];
    if (l == 0) warp_s2[w] = s2;
    __syncthreads();
    float inv2 = rsqrtf(warp_s2[0] + warp_s2[1] + warp_s2[2] + warp_s2[3]);
    float nf = nf1 * inv2;

    // persona-weighted scalars (redundant across threads; 48 fmas, negligible)
    float a = 0.f, b = 0.f, g = 0.f;
    #pragma unroll
    for (int k = 0; k < PP; k++) {
        float p = persona_t[row * PP + k];
        a = fmaf(p, alpha[k], a);
        b = fmaf(p, beta[k],  b);
        g = fmaf(p, gamma[k], g);
    }
    if (t == 0) g_nbeta[row] = -b;

    size_t base = (size_t)row * 2 * FF;
    g_u[base + t]      = a * nf;
    g_u[base + FF + t] = (g * (1.0f / FF)) * d;
    g_v[base + t]      = nf;
    g_v[base + FF + t] = d;
}

// warp per act-edge: 256-length dot of u[src], v[dst] (u,v are L2-resident)
__global__ void act_kernel(const int* __restrict__ act_src,
                           const int* __restrict__ act_dst,
                           float* __restrict__ out, int E) {
    int gid  = blockIdx.x * blockDim.x + threadIdx.x;
    int warp = gid >> 5;
    int lane = gid & 31;
    if (warp >= E) return;
    int src = __ldg(&act_src[warp]);
    int dst = __ldg(&act_dst[warp]);
    const float4* u = (const float4*)(g_u + (size_t)src * 2 * FF);
    const float4* v = (const float4*)(g_v + (size_t)dst * 2 * FF);
    float4 u0 = u[lane * 2],     v0 = v[lane * 2];
    float4 u1 = u[lane * 2 + 1], v1 = v[lane * 2 + 1];
    float s = u0.x * v0.x + u0.y * v0.y + u0.z * v0.z + u0.w * v0.w;
    s = fmaf(u1.x, v1.x, s);
    s = fmaf(u1.y, v1.y, s);
    s = fmaf(u1.z, v1.z, s);
    s = fmaf(u1.w, v1.w, s);
    #pragma unroll
    for (int o = 16; o; o >>= 1) s += __shfl_xor_sync(0xffffffffu, s, o);
    if (lane == 0) atomicAdd(&out[(size_t)src * NN + dst], s);
}

// 2 cost-edges per thread: out[src,dst] += (-beta_row[src])
__global__ void cost_kernel(const int* __restrict__ edge_src,
                            const int* __restrict__ edge_dst,
                            float* __restrict__ out, int E) {
    int e = (blockIdx.x * blockDim.x + threadIdx.x) * 2;
    #pragma unroll
    for (int i = 0; i < 2; i++, e++) {
        if (e < E) {
            int src = __ldg(&edge_src[e]);
            int dst = __ldg(&edge_dst[e]);
            atomicAdd(&out[(size_t)src * NN + dst], g_nbeta[src]);
        }
    }
}

extern "C" void kernel_launch(void* const* d_in, const int* in_sizes, int n_in,
                              void* d_out, int out_size) {
    const float* feature      = (const float*)d_in[0];
    const float* next_feature = (const float*)d_in[1];
    const float* persona_t    = (const float*)d_in[2];
    const float* alpha        = (const float*)d_in[3];
    const float* beta         = (const float*)d_in[4];
    const float* gamma        = (const float*)d_in[5];
    const int*   act_src      = (const int*)d_in[6];
    const int*   act_dst      = (const int*)d_in[7];
    const int*   edge_src     = (const int*)d_in[8];
    const int*   edge_dst     = (const int*)d_in[9];
    float* out = (float*)d_out;
    int E  = in_sizes[6];
    int Ec = in_sizes[8];

    cudaMemsetAsync(out, 0, (size_t)out_size * sizeof(float));
    prep_kernel<<<NN, FF>>>(feature, next_feature, persona_t, alpha, beta, gamma);
    // 8 warps (8 edges) per 256-thread block
    int act_blocks = (E + 7) / 8;
    act_kernel<<<act_blocks, 256>>>(act_src, act_dst, out, E);
    int cost_threads = (Ec + 1) / 2;
    cost_kernel<<<(cost_threads + 255) / 256, 256>>>(edge_src, edge_dst, out, Ec);
}

// round 7
// speedup vs baseline: 1.2603x; 1.2603x over previous
#include <cuda_runtime.h>
#include <cuda_fp16.h>

#define NN 8192
#define FF 128
#define PP 16
#define EMAX 262144

// u16[i] = fp16 concat(alpha_row[i]*nf_i, (gamma_row[i]/F)*diff_i)  (256 halves = 512B/row)
// v32[i] = fp32 concat(nf_i, diff_i)                                 (256 floats = 1KB/row)
// act-edge value = dot(u16[src], v32[dst])
__device__ __half g_u[NN * 2 * FF];
__device__ float  g_v[NN * 2 * FF];
__device__ float  g_nbeta[NN];     // -beta_row
__device__ float  g_val[EMAX];     // per-act-edge values

static __device__ __forceinline__ unsigned h2_bits(__half2 h) {
    return *reinterpret_cast<unsigned*>(&h);
}

// ---------------- prep: warp per row, shfl-only ----------------
__global__ void prep_kernel(const float* __restrict__ feature,
                            const float* __restrict__ next_feature,
                            const float* __restrict__ persona_t,
                            const float* __restrict__ alpha,
                            const float* __restrict__ beta,
                            const float* __restrict__ gamma) {
    int warp = (blockIdx.x * blockDim.x + threadIdx.x) >> 5;
    int lane = threadIdx.x & 31;
    if (warp >= NN) return;
    int row = warp;

    const float4* nf4 = (const float4*)(next_feature + (size_t)row * FF);
    const float4* f4  = (const float4*)(feature      + (size_t)row * FF);
    float4 nf = nf4[lane];
    float4 f  = f4[lane];
    float4 d  = make_float4(f.x - nf.x, f.y - nf.y, f.z - nf.z, f.w - nf.w);

    // first L2 normalize
    float ss = nf.x*nf.x + nf.y*nf.y + nf.z*nf.z + nf.w*nf.w;
    #pragma unroll
    for (int o = 16; o; o >>= 1) ss += __shfl_xor_sync(0xffffffffu, ss, o);
    float inv = rsqrtf(ss);
    nf.x *= inv; nf.y *= inv; nf.z *= inv; nf.w *= inv;
    // second normalize (reference does it twice; replicate fp rounding)
    float s2 = nf.x*nf.x + nf.y*nf.y + nf.z*nf.z + nf.w*nf.w;
    #pragma unroll
    for (int o = 16; o; o >>= 1) s2 += __shfl_xor_sync(0xffffffffu, s2, o);
    float inv2 = rsqrtf(s2);
    nf.x *= inv2; nf.y *= inv2; nf.z *= inv2; nf.w *= inv2;

    // persona-weighted scalars: lanes 0..15 contribute, shfl-reduce
    float pa = 0.f, pb = 0.f, pg = 0.f;
    if (lane < PP) {
        float p = persona_t[(size_t)row * PP + lane];
        pa = p * alpha[lane];
        pb = p * beta[lane];
        pg = p * gamma[lane];
    }
    #pragma unroll
    for (int o = 16; o; o >>= 1) {
        pa += __shfl_xor_sync(0xffffffffu, pa, o);
        pb += __shfl_xor_sync(0xffffffffu, pb, o);
        pg += __shfl_xor_sync(0xffffffffu, pg, o);
    }
    if (lane == 0) g_nbeta[row] = -pb;
    float gg = pg * (1.0f / FF);

    // v: fp32 [nf | d]
    float4* vrow = (float4*)(g_v + (size_t)row * 2 * FF);
    vrow[lane]      = nf;
    vrow[32 + lane] = d;

    // u: fp16 [pa*nf | gg*d], 4 halves per lane per half-row (8B stores)
    uint2* urow = (uint2*)(g_u + (size_t)row * 2 * FF);
    __half2 h0 = __floats2half2_rn(pa * nf.x, pa * nf.y);
    __half2 h1 = __floats2half2_rn(pa * nf.z, pa * nf.w);
    urow[lane] = make_uint2(h2_bits(h0), h2_bits(h1));
    __half2 h2 = __floats2half2_rn(gg * d.x, gg * d.y);
    __half2 h3 = __floats2half2_rn(gg * d.z, gg * d.w);
    urow[32 + lane] = make_uint2(h2_bits(h2), h2_bits(h3));
}

// ------------- fused: zero-fill output + warp-per-edge dots -------------
__global__ void zero_act_kernel(const int* __restrict__ act_src,
                                const int* __restrict__ act_dst,
                                float* __restrict__ out,
                                long total, int E) {
    long nthreads = (long)gridDim.x * blockDim.x;
    long gid = (long)blockIdx.x * blockDim.x + threadIdx.x;

    // phase A: grid-stride zero (fire-and-forget stores)
    float4 z = make_float4(0.f, 0.f, 0.f, 0.f);
    float4* o4 = (float4*)out;
    long n4 = total >> 2;
    for (long i = gid; i < n4; i += nthreads) o4[i] = z;
    for (long i = (n4 << 2) + gid; i < total; i += nthreads) out[i] = 0.f;

    // phase B: warp per act edge
    int warp = (int)(gid >> 5);
    int lane = threadIdx.x & 31;
    if (warp >= E) return;
    int src = __ldg(&act_src[warp]);
    int dst = __ldg(&act_dst[warp]);

    const uint4*  u = (const uint4*)(g_u + (size_t)src * 2 * FF);   // 32 x 16B (8 halves/lane)
    const float4* v = (const float4*)(g_v + (size_t)dst * 2 * FF);  // 64 x 16B

    uint4  up = u[lane];
    float4 v0 = v[lane * 2];
    float4 v1 = v[lane * 2 + 1];

    float2 a0 = __half22float2(*(__half2*)&up.x);
    float2 a1 = __half22float2(*(__half2*)&up.y);
    float2 a2 = __half22float2(*(__half2*)&up.z);
    float2 a3 = __half22float2(*(__half2*)&up.w);

    float s;
    s = a0.x * v0.x;
    s = fmaf(a0.y, v0.y, s);
    s = fmaf(a1.x, v0.z, s);
    s = fmaf(a1.y, v0.w, s);
    s = fmaf(a2.x, v1.x, s);
    s = fmaf(a2.y, v1.y, s);
    s = fmaf(a3.x, v1.z, s);
    s = fmaf(a3.y, v1.w, s);
    #pragma unroll
    for (int o = 16; o; o >>= 1) s += __shfl_xor_sync(0xffffffffu, s, o);
    if (lane == 0) g_val[warp] = s;
}

// ------------- scatter: act values + cost atomics -------------
__global__ void scatter_kernel(const int* __restrict__ act_src,
                               const int* __restrict__ act_dst,
                               const int* __restrict__ edge_src,
                               const int* __restrict__ edge_dst,
                               float* __restrict__ out, int E, int Ec) {
    int t = blockIdx.x * blockDim.x + threadIdx.x;
    if (t < E) {
        int src = __ldg(&act_src[t]);
        int dst = __ldg(&act_dst[t]);
        atomicAdd(&out[(size_t)src * NN + dst], g_val[t]);
    } else if (t < E + Ec) {
        int e = t - E;
        int src = __ldg(&edge_src[e]);
        int dst = __ldg(&edge_dst[e]);
        atomicAdd(&out[(size_t)src * NN + dst], g_nbeta[src]);
    }
}

extern "C" void kernel_launch(void* const* d_in, const int* in_sizes, int n_in,
                              void* d_out, int out_size) {
    const float* feature      = (const float*)d_in[0];
    const float* next_feature = (const float*)d_in[1];
    const float* persona_t    = (const float*)d_in[2];
    const float* alpha        = (const float*)d_in[3];
    const float* beta         = (const float*)d_in[4];
    const float* gamma        = (const float*)d_in[5];
    const int*   act_src      = (const int*)d_in[6];
    const int*   act_dst      = (const int*)d_in[7];
    const int*   edge_src     = (const int*)d_in[8];
    const int*   edge_dst     = (const int*)d_in[9];
    float* out = (float*)d_out;
    int E  = in_sizes[6];
    int Ec = in_sizes[8];

    // prep: warp per row, 8 rows per 256-thread block
    prep_kernel<<<(NN + 7) / 8, 256>>>(feature, next_feature, persona_t,
                                       alpha, beta, gamma);

    // fused zero + act dots: 8 edges per 256-thread block
    int fb = (E + 7) / 8;
    zero_act_kernel<<<fb, 256>>>(act_src, act_dst, out, (long)out_size, E);

    // scatter atomics
    int st = E + Ec;
    scatter_kernel<<<(st + 255) / 256, 256>>>(act_src, act_dst, edge_src, edge_dst,
                                              out, E, Ec);
}

// round 10
// speedup vs baseline: 1.3196x; 1.0470x over previous
#include <cuda_runtime.h>
#include <cuda_fp16.h>

#define NN 8192
#define FF 128
#define PP 16
#define EMAX 262144

// u16[i] = fp16 concat(alpha_row[i]*nf_i, (gamma_row[i]/F)*diff_i)  (256 halves = 512B/row)
// v16[i] = fp16 concat(nf_i, diff_i)                                 (256 halves = 512B/row)
// act-edge value = dot(u16[src], v16[dst]), fp32 accumulate
__device__ __half g_u[NN * 2 * FF];
__device__ __half g_v[NN * 2 * FF];
__device__ float  g_nbeta[NN];     // -beta_row
__device__ float  g_val[EMAX];     // per-act-edge values

static __device__ __forceinline__ unsigned h2_bits(__half2 h) {
    return *reinterpret_cast<unsigned*>(&h);
}

// ---------------- prep: warp per row, shfl-only ----------------
__global__ void prep_kernel(const float* __restrict__ feature,
                            const float* __restrict__ next_feature,
                            const float* __restrict__ persona_t,
                            const float* __restrict__ alpha,
                            const float* __restrict__ beta,
                            const float* __restrict__ gamma) {
    int warp = (blockIdx.x * blockDim.x + threadIdx.x) >> 5;
    int lane = threadIdx.x & 31;
    if (warp >= NN) return;
    int row = warp;

    const float4* nf4 = (const float4*)(next_feature + (size_t)row * FF);
    const float4* f4  = (const float4*)(feature      + (size_t)row * FF);
    float4 nf = nf4[lane];
    float4 f  = f4[lane];
    float4 d  = make_float4(f.x - nf.x, f.y - nf.y, f.z - nf.z, f.w - nf.w);

    // first L2 normalize
    float ss = nf.x*nf.x + nf.y*nf.y + nf.z*nf.z + nf.w*nf.w;
    #pragma unroll
    for (int o = 16; o; o >>= 1) ss += __shfl_xor_sync(0xffffffffu, ss, o);
    float inv = rsqrtf(ss);
    nf.x *= inv; nf.y *= inv; nf.z *= inv; nf.w *= inv;
    // second normalize (reference does it twice; replicate fp rounding)
    float s2 = nf.x*nf.x + nf.y*nf.y + nf.z*nf.z + nf.w*nf.w;
    #pragma unroll
    for (int o = 16; o; o >>= 1) s2 += __shfl_xor_sync(0xffffffffu, s2, o);
    float inv2 = rsqrtf(s2);
    nf.x *= inv2; nf.y *= inv2; nf.z *= inv2; nf.w *= inv2;

    // persona-weighted scalars: lanes 0..15 contribute, shfl-reduce
    float pa = 0.f, pb = 0.f, pg = 0.f;
    if (lane < PP) {
        float p = persona_t[(size_t)row * PP + lane];
        pa = p * alpha[lane];
        pb = p * beta[lane];
        pg = p * gamma[lane];
    }
    #pragma unroll
    for (int o = 16; o; o >>= 1) {
        pa += __shfl_xor_sync(0xffffffffu, pa, o);
        pb += __shfl_xor_sync(0xffffffffu, pb, o);
        pg += __shfl_xor_sync(0xffffffffu, pg, o);
    }
    if (lane == 0) g_nbeta[row] = -pb;
    float gg = pg * (1.0f / FF);

    size_t base = (size_t)row * 2 * FF;

    // u: fp16 [pa*nf | gg*d]
    uint2* urow = (uint2*)(g_u + base);
    urow[lane]      = make_uint2(h2_bits(__floats2half2_rn(pa * nf.x, pa * nf.y)),
                                 h2_bits(__floats2half2_rn(pa * nf.z, pa * nf.w)));
    urow[32 + lane] = make_uint2(h2_bits(__floats2half2_rn(gg * d.x, gg * d.y)),
                                 h2_bits(__floats2half2_rn(gg * d.z, gg * d.w)));

    // v: fp16 [nf | d]
    uint2* vrow = (uint2*)(g_v + base);
    vrow[lane]      = make_uint2(h2_bits(__floats2half2_rn(nf.x, nf.y)),
                                 h2_bits(__floats2half2_rn(nf.z, nf.w)));
    vrow[32 + lane] = make_uint2(h2_bits(__floats2half2_rn(d.x, d.y)),
                                 h2_bits(__floats2half2_rn(d.z, d.w)));
}

// ------------- fused: zero-fill output + warp-per-edge dots -------------
__global__ void zero_act_kernel(const int* __restrict__ act_src,
                                const int* __restrict__ act_dst,
                                float* __restrict__ out,
                                long total, int E) {
    long nthreads = (long)gridDim.x * blockDim.x;
    long gid = (long)blockIdx.x * blockDim.x + threadIdx.x;

    // phase A: grid-stride zero (fire-and-forget stores)
    float4 z = make_float4(0.f, 0.f, 0.f, 0.f);
    float4* o4 = (float4*)out;
    long n4 = total >> 2;
    for (long i = gid; i < n4; i += nthreads) o4[i] = z;
    for (long i = (n4 << 2) + gid; i < total; i += nthreads) out[i] = 0.f;

    // phase B: warp per act edge (u,v rows are 512B, L2-resident)
    int warp = (int)(gid >> 5);
    int lane = threadIdx.x & 31;
    if (warp >= E) return;
    int src = __ldg(&act_src[warp]);
    int dst = __ldg(&act_dst[warp]);

    const uint4* u = (const uint4*)(g_u + (size_t)src * 2 * FF);  // 32 x 16B
    const uint4* v = (const uint4*)(g_v + (size_t)dst * 2 * FF);  // 32 x 16B

    uint4 up = u[lane];
    uint4 vp = v[lane];

    float2 a0 = __half22float2(*(__half2*)&up.x);
    float2 a1 = __half22float2(*(__half2*)&up.y);
    float2 a2 = __half22float2(*(__half2*)&up.z);
    float2 a3 = __half22float2(*(__half2*)&up.w);
    float2 b0 = __half22float2(*(__half2*)&vp.x);
    float2 b1 = __half22float2(*(__half2*)&vp.y);
    float2 b2 = __half22float2(*(__half2*)&vp.z);
    float2 b3 = __half22float2(*(__half2*)&vp.w);

    float s;
    s = a0.x * b0.x;
    s = fmaf(a0.y, b0.y, s);
    s = fmaf(a1.x, b1.x, s);
    s = fmaf(a1.y, b1.y, s);
    s = fmaf(a2.x, b2.x, s);
    s = fmaf(a2.y, b2.y, s);
    s = fmaf(a3.x, b3.x, s);
    s = fmaf(a3.y, b3.y, s);
    #pragma unroll
    for (int o = 16; o; o >>= 1) s += __shfl_xor_sync(0xffffffffu, s, o);
    if (lane == 0) g_val[warp] = s;
}

// ------------- scatter: act values + cost atomics -------------
__global__ void scatter_kernel(const int* __restrict__ act_src,
                               const int* __restrict__ act_dst,
                               const int* __restrict__ edge_src,
                               const int* __restrict__ edge_dst,
                               float* __restrict__ out, int E, int Ec) {
    int t = blockIdx.x * blockDim.x + threadIdx.x;
    if (t < E) {
        int src = __ldg(&act_src[t]);
        int dst = __ldg(&act_dst[t]);
        atomicAdd(&out[(size_t)src * NN + dst], g_val[t]);
    } else if (t < E + Ec) {
        int e = t - E;
        int src = __ldg(&edge_src[e]);
        int dst = __ldg(&edge_dst[e]);
        atomicAdd(&out[(size_t)src * NN + dst], g_nbeta[src]);
    }
}

extern "C" void kernel_launch(void* const* d_in, const int* in_sizes, int n_in,
                              void* d_out, int out_size) {
    const float* feature      = (const float*)d_in[0];
    const float* next_feature = (const float*)d_in[1];
    const float* persona_t    = (const float*)d_in[2];
    const float* alpha        = (const float*)d_in[3];
    const float* beta         = (const float*)d_in[4];
    const float* gamma        = (const float*)d_in[5];
    const int*   act_src      = (const int*)d_in[6];
    const int*   act_dst      = (const int*)d_in[7];
    const int*   edge_src     = (const int*)d_in[8];
    const int*   edge_dst     = (const int*)d_in[9];
    float* out = (float*)d_out;
    int E  = in_sizes[6];
    int Ec = in_sizes[8];

    // prep: warp per row, 8 rows per 256-thread block
    prep_kernel<<<(NN + 7) / 8, 256>>>(feature, next_feature, persona_t,
                                       alpha, beta, gamma);

    // fused zero + act dots: 8 edges per 256-thread block
    int fb = (E + 7) / 8;
    zero_act_kernel<<<fb, 256>>>(act_src, act_dst, out, (long)out_size, E);

    // scatter atomics
    int st = E + Ec;
    scatter_kernel<<<(st + 255) / 256, 256>>>(act_src, act_dst, edge_src, edge_dst,
                                              out, E, Ec);
}